// round 1
// baseline (speedup 1.0000x reference)
#include <cuda_runtime.h>
#include <math.h>

#define T_LEN 2000
#define FC 514            // 257 * 2
#define NSER 8224         // 16 * 514
#define U 40              // time chunk per prefetch buffer
#define NCHUNK (T_LEN/U)  // 50 (even)

// Per-t coefficients: (w, 1-w, w*(1-w), 0)
__device__ float4 g_coef[T_LEN];

__global__ void coef_kernel() {
    int t = blockIdx.x * blockDim.x + threadIdx.x;
    if (t >= T_LEN) return;
    // beta is float32(0.99) in the reference; compute powers exactly in double.
    double b  = (double)0.99f;
    double c1 = (double)(1.0f - 0.99f);     // exact (Sterbenz)
    double bt = pow(b, (double)(t + 1));
    double e  = 1.0 - bt;
    double w  = c1 / e;                     // w_0 == 1 exactly
    double om = 1.0 - w;
    double wom = w * om;
    g_coef[t] = make_float4((float)w, (float)om, (float)wom, 0.0f);
}

__global__ __launch_bounds__(64)
void ewma_kernel(const float* __restrict__ in, float* __restrict__ out) {
    __shared__ float4 scoef[T_LEN];   // 32 KB, broadcast reads
    for (int i = threadIdx.x; i < T_LEN; i += 64) scoef[i] = g_coef[i];
    __syncthreads();

    int ser = blockIdx.x * 64 + threadIdx.x;
    if (ser >= NSER) return;
    int n  = ser / FC;
    int fc = ser - n * FC;
    const float* xp = in  + (size_t)n * T_LEN * FC + fc;
    float*       yp = out + (size_t)n * T_LEN * FC + fc;

    float v2 = 0.0f, S = 0.0f;
    float xa[U], xb[U];

    // preload chunk 0
#pragma unroll
    for (int u = 0; u < U; u++) xa[u] = __ldg(xp + (size_t)u * FC);

    for (int k = 0; k < NCHUNK; k += 2) {
        // prefetch chunk k+1 into xb (covers DRAM latency behind compute)
        {
            const float* p = xp + (size_t)(k + 1) * U * FC;
#pragma unroll
            for (int u = 0; u < U; u++) xb[u] = __ldg(p + (size_t)u * FC);
        }
        // compute chunk k from xa
        {
            int tb = k * U;
            float* yb = yp + (size_t)tb * FC;
#pragma unroll
            for (int u = 0; u < U; u++) {
                float4 c = scoef[tb + u];       // (w, om, wom)
                float x  = xa[u];
                float d2 = x - v2;              // x - v2_prev
                v2 = fmaf(c.x, d2, v2);         // v2 = (1-w)v2 + w x
                float wq = c.z * (d2 * d2);     // w*(1-w)*d2^2  (= w * p)
                S  = fmaf(c.y, S, wq);          // S = (1-w)S + w p   (p >= 0 => clamp no-op on carry)
                float Sc = fmaxf(S, 0.0f);      // clamp for the output path only
                float d1 = c.y * d2;            // x - v2_new = (1-w) d2
                float y  = d1 * rsqrtf(Sc + 1e-5f);
                __stcs(yb + (size_t)u * FC, y); // streaming store: keep input in L2
            }
        }
        // prefetch chunk k+2 into xa
        if (k + 2 < NCHUNK) {
            const float* p = xp + (size_t)(k + 2) * U * FC;
#pragma unroll
            for (int u = 0; u < U; u++) xa[u] = __ldg(p + (size_t)u * FC);
        }
        // compute chunk k+1 from xb
        {
            int tb = (k + 1) * U;
            float* yb = yp + (size_t)tb * FC;
#pragma unroll
            for (int u = 0; u < U; u++) {
                float4 c = scoef[tb + u];
                float x  = xb[u];
                float d2 = x - v2;
                v2 = fmaf(c.x, d2, v2);
                float wq = c.z * (d2 * d2);
                S  = fmaf(c.y, S, wq);
                float Sc = fmaxf(S, 0.0f);
                float d1 = c.y * d2;
                float y  = d1 * rsqrtf(Sc + 1e-5f);
                __stcs(yb + (size_t)u * FC, y);
            }
        }
    }
}

extern "C" void kernel_launch(void* const* d_in, const int* in_sizes, int n_in,
                              void* d_out, int out_size) {
    const float* s = (const float*)d_in[0];
    float* out = (float*)d_out;
    coef_kernel<<<(T_LEN + 127) / 128, 128>>>();
    // blockDim=64 (2 warps -> SMSP 0 and 1), grid=129 <= 148 SMs:
    // at most one block per SM, so no SMSP hosts two warps.
    ewma_kernel<<<129, 64>>>(s, out);
}

// round 2
// speedup vs baseline: 1.9620x; 1.9620x over previous
#include <cuda_runtime.h>
#include <math.h>

#define T_LEN 2000
#define FC    514           // 257 * 2
#define NSER  8224          // 16 * 514
#define CH    40            // number of time chunks
#define LCH   50            // chunk length (CH*LCH == T_LEN)

// Per-t coefficients: (w, a=1-w, b=w*(1-w), 0)
__device__ float4 g_coef[T_LEN];
// Per (chunk, series) scratch
__device__ float2 g_pq [CH * NSER];   // (P, Q)
__device__ float4 g_abg[CH * NSER];   // (alpha, beta, gamma, -)
__device__ float2 g_vs [CH * NSER];   // (v2_start, S_start) per chunk

__global__ void coef_kernel() {
    int t = blockIdx.x * blockDim.x + threadIdx.x;
    if (t >= T_LEN) return;
    double b  = (double)0.99f;
    double c1 = (double)(1.0f - 0.99f);   // exact
    double bt = pow(b, (double)(t + 1));
    double e  = 1.0 - bt;
    double w  = c1 / e;                   // w_0 == 1 exactly
    double a  = 1.0 - w;
    g_coef[t] = make_float4((float)w, (float)a, (float)(w * a), 0.0f);
}

// Pass 1: per (chunk, series) compute transfer coefficients.
__global__ __launch_bounds__(256)
void pass1_kernel(const float* __restrict__ in) {
    int ser = blockIdx.x * 256 + threadIdx.x;
    int c   = blockIdx.y;
    if (ser >= NSER) return;
    int n  = ser / FC;
    int fc = ser - n * FC;
    const float* xp = in + ((size_t)n * T_LEN + (size_t)c * LCH) * FC + fc;
    int t0 = c * LCH;

    float P = 1.0f, Q = 0.0f, al = 0.0f, be = 0.0f, ga = 0.0f;
#pragma unroll 10
    for (int u = 0; u < LCH; u++) {
        float4 cf = __ldg(&g_coef[t0 + u]);      // (w, a, b)
        float  x  = __ldg(xp + (size_t)u * FC);
        float  uu = x - Q;                       // u_t = x - Q_{t-1}
        Q  = fmaf(cf.x, uu, Q);                  // Q += w*u
        float bu = cf.z * uu;                    // b*u
        al = fmaf(cf.y, al, bu * uu);            // a*al + b*u^2
        be = fmaf(cf.y, be, bu * P);             // a*be + b*u*P_{t-1}
        float bP = cf.z * P;
        ga = fmaf(cf.y, ga, bP * P);             // a*ga + b*P_{t-1}^2
        P  = cf.y * P;                           // P *= a
    }
    int idx = c * NSER + ser;
    g_pq [idx] = make_float2(P, Q);
    g_abg[idx] = make_float4(al, be, ga, 0.0f);
}

// Combine: serial over the 40 chunks per series (cheap).
__global__ __launch_bounds__(256)
void combine_kernel() {
    int ser = blockIdx.x * 256 + threadIdx.x;
    if (ser >= NSER) return;
    float v2 = 0.0f, S = 0.0f;
#pragma unroll 4
    for (int c = 0; c < CH; c++) {
        int idx = c * NSER + ser;
        float2 pq = __ldg(&g_pq [idx]);
        float4 ab = __ldg(&g_abg[idx]);
        g_vs[idx] = make_float2(v2, S);
        // S' = P*S + alpha + v2*(gamma*v2 - 2*beta);  v2' = P*v2 + Q
        float corr = fmaf(ab.z, v2, -2.0f * ab.y);
        float add  = fmaf(v2, corr, ab.x);
        S  = fmaf(pq.x, S, add);
        v2 = fmaf(pq.x, v2, pq.y);
    }
}

// Pass 2: replay each chunk with exact start state, emit outputs.
__global__ __launch_bounds__(256)
void pass2_kernel(const float* __restrict__ in, float* __restrict__ out) {
    int ser = blockIdx.x * 256 + threadIdx.x;
    int c   = blockIdx.y;
    if (ser >= NSER) return;
    int n  = ser / FC;
    int fc = ser - n * FC;
    size_t base = ((size_t)n * T_LEN + (size_t)c * LCH) * FC + fc;
    const float* xp = in  + base;
    float*       yp = out + base;
    int t0 = c * LCH;

    float2 vs = __ldg(&g_vs[c * NSER + ser]);
    float v2 = vs.x, S = vs.y;
#pragma unroll 10
    for (int u = 0; u < LCH; u++) {
        float4 cf = __ldg(&g_coef[t0 + u]);      // (w, a, b)
        float  x  = __ldg(xp + (size_t)u * FC);
        float d2 = x - v2;                       // x - v2_prev
        v2 = fmaf(cf.x, d2, v2);                 // v2 = a*v2 + w*x
        S  = fmaf(cf.y, S, cf.z * (d2 * d2));    // S = a*S + b*d2^2
        float Sc = fmaxf(S, 0.0f);
        float y  = (cf.y * d2) * rsqrtf(Sc + 1e-5f);
        __stcs(yp + (size_t)u * FC, y);
    }
}

extern "C" void kernel_launch(void* const* d_in, const int* in_sizes, int n_in,
                              void* d_out, int out_size) {
    const float* s = (const float*)d_in[0];
    float* out = (float*)d_out;
    coef_kernel<<<(T_LEN + 127) / 128, 128>>>();
    dim3 grid((NSER + 255) / 256, CH);
    pass1_kernel<<<grid, 256>>>(s);
    combine_kernel<<<(NSER + 255) / 256, 256>>>();
    pass2_kernel<<<grid, 256>>>(s, out);
}